// round 1
// baseline (speedup 1.0000x reference)
#include <cuda_runtime.h>
#include <cstdint>
#include <cmath>

// Problem constants (fixed by setup_inputs)
#define B_   8
#define NQ_  8192
#define E_   256
#define HN_  8
#define P_   4
#define DH_  32
#define NV_  16384   // 128*128

// Scratch (no cudaMalloc allowed)
__device__ float g_v  [(size_t)B_ * NV_ * E_];          // projected value (B, NV, E)
__device__ float g_off[(size_t)B_ * NQ_ * HN_ * P_ * 2]; // sampling offsets
__device__ float g_att[(size_t)B_ * NQ_ * HN_ * P_];     // attn logits
__device__ float g_o  [(size_t)B_ * NQ_ * E_];           // sampled output pre-proj

// ---------------------------------------------------------------------------
// Tiled fp32 GEMM: C = A(MxK) * Bw(KxN) + bias[N]  (+ R if RESID)
// BM=128, BN=64, BK=16, 256 threads, 8x4 register tile per thread.
// K must be a multiple of 16 (always 256 here). M multiple of 128 here.
// ---------------------------------------------------------------------------
template<bool RESID>
__global__ __launch_bounds__(256)
void gemm_kernel(const float* __restrict__ A, const float* __restrict__ Bw,
                 const float* __restrict__ bias, const float* __restrict__ R,
                 float* __restrict__ C, int M, int N, int K)
{
    constexpr int BM = 128, BN = 64, BK = 16, TM = 8, TN = 4;
    __shared__ float As[BK][BM + 4];
    __shared__ float Bs[BK][BN];

    const int tid = threadIdx.x;
    const int tx  = tid & 15;      // 16 cols of threads
    const int ty  = tid >> 4;      // 16 rows of threads
    const int row0 = blockIdx.y * BM;
    const int col0 = blockIdx.x * BN;

    float acc[TM][TN];
#pragma unroll
    for (int i = 0; i < TM; i++)
#pragma unroll
        for (int j = 0; j < TN; j++) acc[i][j] = 0.f;

    for (int k0 = 0; k0 < K; k0 += BK) {
        // Load A tile: 128x16 = 2048 elems, 8 per thread
#pragma unroll
        for (int i = 0; i < 8; i++) {
            int idx = tid + i * 256;
            int ar = idx >> 4;        // 0..127
            int ac = idx & 15;        // 0..15
            int gr = row0 + ar;
            As[ac][ar] = (gr < M) ? A[(size_t)gr * K + (k0 + ac)] : 0.f;
        }
        // Load B tile: 16x64 = 1024 elems, 4 per thread
#pragma unroll
        for (int i = 0; i < 4; i++) {
            int idx = tid + i * 256;
            int br = idx >> 6;        // 0..15
            int bc = idx & 63;        // 0..63
            int gc = col0 + bc;
            Bs[br][bc] = (gc < N) ? Bw[(size_t)(k0 + br) * N + gc] : 0.f;
        }
        __syncthreads();

#pragma unroll
        for (int kk = 0; kk < BK; kk++) {
            float ra[TM], rb[TN];
#pragma unroll
            for (int i = 0; i < TM; i++) ra[i] = As[kk][ty * TM + i];
#pragma unroll
            for (int j = 0; j < TN; j++) rb[j] = Bs[kk][tx * TN + j];
#pragma unroll
            for (int i = 0; i < TM; i++)
#pragma unroll
                for (int j = 0; j < TN; j++)
                    acc[i][j] = fmaf(ra[i], rb[j], acc[i][j]);
        }
        __syncthreads();
    }

#pragma unroll
    for (int i = 0; i < TM; i++) {
        int gr = row0 + ty * TM + i;
        if (gr >= M) continue;
#pragma unroll
        for (int j = 0; j < TN; j++) {
            int gc = col0 + tx * TN + j;
            if (gc >= N) continue;
            float v = acc[i][j] + bias[gc];
            if (RESID) v += R[(size_t)gr * N + gc];
            C[(size_t)gr * N + gc] = v;
        }
    }
}

// ---------------------------------------------------------------------------
// Sampling: one warp per (b, q, h). lane = channel within head (dh=32).
// Reads g_off / g_att / g_v, writes g_o.
// ---------------------------------------------------------------------------
__global__ __launch_bounds__(256)
void sample_kernel(const float* __restrict__ ref2d, const int* __restrict__ shapes)
{
    const int gtid = blockIdx.x * blockDim.x + threadIdx.x;
    const int warp = gtid >> 5;
    const int lane = gtid & 31;
    const int h  = warp & (HN_ - 1);
    const int bq = warp >> 3;
    if (bq >= B_ * NQ_) return;
    const int b = bq >> 13;                 // NQ_ = 8192

    const int Hl = shapes[0], Wl = shapes[1];
    const float fW = (float)Wl, fH = (float)Hl;

    const float rx = ref2d[(size_t)bq * 2 + 0];
    const float ry = ref2d[(size_t)bq * 2 + 1];

    // Softmax over P=4 logits for this head
    float lg[P_];
    float mx = -1e30f;
#pragma unroll
    for (int p = 0; p < P_; p++) {
        lg[p] = g_att[(size_t)bq * (HN_ * P_) + h * P_ + p];
        mx = fmaxf(mx, lg[p]);
    }
    float s = 0.f;
    float a[P_];
#pragma unroll
    for (int p = 0; p < P_; p++) { a[p] = expf(lg[p] - mx); s += a[p]; }
    const float inv = 1.f / s;
#pragma unroll
    for (int p = 0; p < P_; p++) a[p] *= inv;

    const float* vb = g_v + (size_t)b * NV_ * E_ + h * DH_ + lane;
    const float* ob = g_off + (size_t)bq * (HN_ * P_ * 2) + h * (P_ * 2);

    float acc = 0.f;
#pragma unroll
    for (int p = 0; p < P_; p++) {
        const float ox = ob[2 * p + 0];
        const float oy = ob[2 * p + 1];
        const float x = (rx + ox / fW) * fW - 0.5f;
        const float y = (ry + oy / fH) * fH - 0.5f;
        const float x0f = floorf(x), y0f = floorf(y);
        const int x0 = (int)x0f, y0 = (int)y0f;
        const float wx1 = x - x0f, wx0 = 1.f - wx1;
        const float wy1 = y - y0f, wy0 = 1.f - wy1;
        const float ap = a[p];

        const int   xc[4] = { x0, x0 + 1, x0,     x0 + 1 };
        const int   yc[4] = { y0, y0,     y0 + 1, y0 + 1 };
        const float wc[4] = { wx0 * wy0, wx1 * wy0, wx0 * wy1, wx1 * wy1 };
#pragma unroll
        for (int c = 0; c < 4; c++) {
            if (xc[c] >= 0 && xc[c] < Wl && yc[c] >= 0 && yc[c] < Hl) {
                acc = fmaf(ap * wc[c], vb[(size_t)(yc[c] * Wl + xc[c]) * E_], acc);
            }
        }
    }

    g_o[(size_t)bq * E_ + h * DH_ + lane] = acc;
}

// ---------------------------------------------------------------------------
extern "C" void kernel_launch(void* const* d_in, const int* in_sizes, int n_in,
                              void* d_out, int out_size)
{
    const float* query  = (const float*)d_in[0];
    const float* value  = (const float*)d_in[1];
    const float* ref2d  = (const float*)d_in[2];
    const int*   shapes = (const int*)  d_in[3];
    const float* W_off  = (const float*)d_in[4];
    const float* b_off  = (const float*)d_in[5];
    const float* W_attn = (const float*)d_in[6];
    const float* b_attn = (const float*)d_in[7];
    const float* W_val  = (const float*)d_in[8];
    const float* b_val  = (const float*)d_in[9];
    const float* W_out  = (const float*)d_in[10];
    const float* b_out  = (const float*)d_in[11];
    float* out = (float*)d_out;

    float *v_ptr, *off_ptr, *att_ptr, *o_ptr;
    cudaGetSymbolAddress((void**)&v_ptr,  g_v);
    cudaGetSymbolAddress((void**)&off_ptr, g_off);
    cudaGetSymbolAddress((void**)&att_ptr, g_att);
    cudaGetSymbolAddress((void**)&o_ptr,  g_o);

    const int Mv = B_ * NV_;   // 131072
    const int Mq = B_ * NQ_;   // 65536

    // 1) value projection: (Mv,256) @ (256,256)
    {
        dim3 grid(E_ / 64, Mv / 128);
        gemm_kernel<false><<<grid, 256>>>(value, W_val, b_val, nullptr, v_ptr, Mv, E_, E_);
    }
    // 2) offset projection: (Mq,256) @ (256,64)
    {
        dim3 grid(1, Mq / 128);
        gemm_kernel<false><<<grid, 256>>>(query, W_off, b_off, nullptr, off_ptr, Mq, 64, E_);
    }
    // 3) attn projection: (Mq,256) @ (256,32)
    {
        dim3 grid(1, Mq / 128);
        gemm_kernel<false><<<grid, 256>>>(query, W_attn, b_attn, nullptr, att_ptr, Mq, 32, E_);
    }
    // 4) softmax + bilinear sampling -> g_o
    {
        int warps = Mq * HN_;                 // 524288
        int blocks = warps * 32 / 256;        // 65536
        sample_kernel<<<blocks, 256>>>(ref2d, shapes);
    }
    // 5) output projection + bias + residual -> d_out
    {
        dim3 grid(E_ / 64, Mq / 128);
        gemm_kernel<true><<<grid, 256>>>(o_ptr, W_out, b_out, query, out, Mq, E_, E_);
    }
}

// round 3
// speedup vs baseline: 2.9877x; 2.9877x over previous
#include <cuda_runtime.h>
#include <cstdint>
#include <cmath>

// Problem constants (fixed by setup_inputs)
#define B_   8
#define NQ_  8192
#define E_   256
#define HN_  8
#define P_   4
#define DH_  32
#define NV_  16384   // 128*128

// Scratch (no cudaMalloc allowed)
__device__ float g_v  [(size_t)B_ * NV_ * E_];           // projected value (B, NV, E)
__device__ float g_off[(size_t)B_ * NQ_ * HN_ * P_ * 2]; // sampling offsets
__device__ float g_att[(size_t)B_ * NQ_ * HN_ * P_];     // attn logits
__device__ float g_o  [(size_t)B_ * NQ_ * E_];           // sampled output pre-proj

// ---------------------------------------------------------------------------
// PTX helpers (arch-neutral: cp.async + mma.sync only; no tcgen05)
// ---------------------------------------------------------------------------
#define CP_ASYNC16(saddr, gaddr) \
    asm volatile("cp.async.cg.shared.global [%0], [%1], 16;" :: "r"(saddr), "l"(gaddr) : "memory")
#define CP_COMMIT() asm volatile("cp.async.commit_group;" ::: "memory")
template<int N>
__device__ __forceinline__ void cp_wait() {
    asm volatile("cp.async.wait_group %0;" :: "n"(N) : "memory");
}

__device__ __forceinline__ uint32_t smem_u32(const void* p) {
    uint32_t a;
    asm("{ .reg .u64 t; cvta.to.shared.u64 t, %1; cvt.u32.u64 %0, t; }" : "=r"(a) : "l"(p));
    return a;
}

// round-to-nearest tf32 conversion (zero-mean quantization error — required;
// raw truncation inside HMMA gives sign-correlated error that blows past 1e-3)
__device__ __forceinline__ uint32_t tf32r(float x) {
    uint32_t o;
    asm("cvt.rna.tf32.f32 %0, %1;" : "=r"(o) : "f"(x));
    return o;
}

__device__ __forceinline__ void mma_tf32(float d[4], const uint32_t a[4],
                                         uint32_t b0, uint32_t b1) {
    asm volatile(
        "mma.sync.aligned.m16n8k8.row.col.f32.tf32.tf32.f32 "
        "{%0,%1,%2,%3}, {%4,%5,%6,%7}, {%8,%9}, {%0,%1,%2,%3};"
        : "+f"(d[0]), "+f"(d[1]), "+f"(d[2]), "+f"(d[3])
        : "r"(a[0]), "r"(a[1]), "r"(a[2]), "r"(a[3]), "r"(b0), "r"(b1));
}

// ---------------------------------------------------------------------------
// GEMM: C(M,N) = A(M,K=256) @ W(K=256,N) + bias (+R if RESID)
// Tile: 128 x BN per CTA, BK=32, 8 warps (warp tile 32 x BN/2), 2-stage cp.async.
// ---------------------------------------------------------------------------
template<int BN, bool RESID>
__global__ __launch_bounds__(256, 2)
void gemm_mma(const float* __restrict__ A, const float* __restrict__ W,
              const float* __restrict__ bias, const float* __restrict__ R,
              float* __restrict__ C, int M, int N)
{
    constexpr int BM = 128, BK = 32, NIT = E_ / BK;       // 8 iterations
    constexpr int AP = BK + 4;                            // 36 floats (144B rows)
    constexpr int BP = BN + 4;
    constexpr int ASZ = BM * AP;                          // floats per A stage
    constexpr int BSZ = BK * BP;
    constexpr int NT  = BN / 16;                          // n-tiles per warp (m16n8 x2 mtiles)

    extern __shared__ float smem[];
    float* const Ast[2] = { smem, smem + ASZ + BSZ };
    float* const Bst[2] = { smem + ASZ, smem + 2 * ASZ + BSZ + (BSZ - BSZ) + BSZ * 0 + ASZ };
    // (rewritten clearly below)
    float* const As0 = smem;
    float* const Bs0 = smem + ASZ;
    float* const As1 = smem + ASZ + BSZ;
    float* const Bs1 = smem + 2 * ASZ + BSZ;

    const int tid  = threadIdx.x;
    const int wid  = tid >> 5;
    const int lane = tid & 31;
    const int gid  = lane >> 2;     // group id 0..7
    const int tig  = lane & 3;      // thread-in-group 0..3

    const int row0 = blockIdx.y * BM;
    const int col0 = blockIdx.x * BN;
    const int wr0  = (wid & 3) * 32;          // warp row within tile
    const int wc0  = (wid >> 2) * (BN / 2);   // warp col within tile

    const uint32_t sA[2] = { smem_u32(As0), smem_u32(As1) };
    const uint32_t sB[2] = { smem_u32(Bs0), smem_u32(Bs1) };

    float acc[2][NT][4];
#pragma unroll
    for (int mt = 0; mt < 2; mt++)
#pragma unroll
        for (int nt = 0; nt < NT; nt++)
#pragma unroll
            for (int i = 0; i < 4; i++) acc[mt][nt][i] = 0.f;

    // ---- loaders ----
    auto load_tile = [&](int s, int k0) {
        // A: 128 x 32 floats, row-major [m][k], 4 float4 per thread
        const float* Ab = A + (size_t)row0 * E_ + k0;
#pragma unroll
        for (int i = 0; i < 4; i++) {
            int idx = tid + i * 256;
            int r = idx >> 3, c4 = idx & 7;
            CP_ASYNC16(sA[s] + (uint32_t)(r * AP + c4 * 4) * 4, Ab + (size_t)r * E_ + c4 * 4);
        }
        // B: 32 x BN floats from W, row-major [k][n]
        const float* Wb = W + (size_t)k0 * N + col0;
#pragma unroll
        for (int i = 0; i < BN / 32; i++) {
            int idx = tid + i * 256;
            int r = idx / (BN / 4), c4 = idx % (BN / 4);
            CP_ASYNC16(sB[s] + (uint32_t)(r * BP + c4 * 4) * 4, Wb + (size_t)r * N + c4 * 4);
        }
    };

    auto compute_tile = [&](int s) {
        const float* Asp = (s == 0) ? As0 : As1;
        const float* Bsp = (s == 0) ? Bs0 : Bs1;
#pragma unroll
        for (int ks = 0; ks < BK / 8; ks++) {
            const int kb = ks * 8 + tig;
            uint32_t af[2][4];
#pragma unroll
            for (int mt = 0; mt < 2; mt++) {
                const int r = wr0 + mt * 16 + gid;
                af[mt][0] = tf32r(Asp[r * AP + kb]);
                af[mt][1] = tf32r(Asp[(r + 8) * AP + kb]);
                af[mt][2] = tf32r(Asp[r * AP + kb + 4]);
                af[mt][3] = tf32r(Asp[(r + 8) * AP + kb + 4]);
            }
#pragma unroll
            for (int nt = 0; nt < NT; nt++) {
                const int c = wc0 + nt * 8 + gid;
                const uint32_t b0 = tf32r(Bsp[kb * BP + c]);
                const uint32_t b1 = tf32r(Bsp[(kb + 4) * BP + c]);
                mma_tf32(acc[0][nt], af[0], b0, b1);
                mma_tf32(acc[1][nt], af[1], b0, b1);
            }
        }
    };

    // ---- pipelined mainloop ----
    load_tile(0, 0); CP_COMMIT();
#pragma unroll
    for (int it = 0; it < NIT; it++) {
        if (it + 1 < NIT) {
            load_tile((it + 1) & 1, (it + 1) * BK); CP_COMMIT();
            cp_wait<1>();
        } else {
            cp_wait<0>();
        }
        __syncthreads();
        compute_tile(it & 1);
        __syncthreads();
    }

    // ---- epilogue: direct float2 stores ----
#pragma unroll
    for (int mt = 0; mt < 2; mt++) {
#pragma unroll
        for (int nt = 0; nt < NT; nt++) {
            const int c = col0 + wc0 + nt * 8 + 2 * tig;
            const float bx = bias[c], by = bias[c + 1];
            const int r0 = row0 + wr0 + mt * 16 + gid;
            float2 o0 = { acc[mt][nt][0] + bx, acc[mt][nt][1] + by };
            float2 o1 = { acc[mt][nt][2] + bx, acc[mt][nt][3] + by };
            if (RESID) {
                const float2 rv0 = *(const float2*)&R[(size_t)r0 * N + c];
                const float2 rv1 = *(const float2*)&R[(size_t)(r0 + 8) * N + c];
                o0.x += rv0.x; o0.y += rv0.y;
                o1.x += rv1.x; o1.y += rv1.y;
            }
            *(float2*)&C[(size_t)r0 * N + c] = o0;
            *(float2*)&C[(size_t)(r0 + 8) * N + c] = o1;
        }
    }
    (void)Ast; (void)Bst;
}

// ---------------------------------------------------------------------------
// Sampling: one warp per (bq, half). lane handles 4 channels (float4).
// half selects heads [half*4, half*4+4); lane>>3 selects head within half.
// ---------------------------------------------------------------------------
__global__ __launch_bounds__(256)
void sample_kernel(const float* __restrict__ ref2d, const int* __restrict__ shapes)
{
    const int gtid = blockIdx.x * blockDim.x + threadIdx.x;
    const int warp = gtid >> 5;
    const int lane = gtid & 31;
    const int bq   = warp >> 1;
    const int half = warp & 1;
    if (bq >= B_ * NQ_) return;
    const int b = bq >> 13;                     // NQ_ = 8192

    const int h  = half * 4 + (lane >> 3);      // head 0..7
    const int c0 = h * DH_ + (lane & 7) * 4;    // channel base (float4)

    const int Hl = shapes[0], Wl = shapes[1];
    const float fW = (float)Wl, fH = (float)Hl;

    const float rx = ref2d[(size_t)bq * 2 + 0];
    const float ry = ref2d[(size_t)bq * 2 + 1];

    // softmax over P=4 logits (vector load; duplicated across 8 lanes of head)
    const float4 lg = *(const float4*)&g_att[(size_t)bq * (HN_ * P_) + h * P_];
    float mx = fmaxf(fmaxf(lg.x, lg.y), fmaxf(lg.z, lg.w));
    float a0 = expf(lg.x - mx), a1 = expf(lg.y - mx),
          a2 = expf(lg.z - mx), a3 = expf(lg.w - mx);
    const float inv = 1.f / (a0 + a1 + a2 + a3);
    float aw[P_] = { a0 * inv, a1 * inv, a2 * inv, a3 * inv };

    // offsets: 8 floats contiguous per (bq, h)
    const float4 of0 = *(const float4*)&g_off[(size_t)bq * (HN_ * P_ * 2) + h * (P_ * 2)];
    const float4 of1 = *(const float4*)&g_off[(size_t)bq * (HN_ * P_ * 2) + h * (P_ * 2) + 4];
    const float ox[P_] = { of0.x, of0.z, of1.x, of1.z };
    const float oy[P_] = { of0.y, of0.w, of1.y, of1.w };

    const float* vb = g_v + (size_t)b * NV_ * E_ + c0;

    float4 acc = { 0.f, 0.f, 0.f, 0.f };
#pragma unroll
    for (int p = 0; p < P_; p++) {
        const float x = fmaf(rx, fW, ox[p]) - 0.5f;  // rx*W + ox - 0.5
        const float y = fmaf(ry, fH, oy[p]) - 0.5f;
        const float x0f = floorf(x), y0f = floorf(y);
        const int x0 = (int)x0f, y0 = (int)y0f;
        const float wx1 = x - x0f, wx0 = 1.f - wx1;
        const float wy1 = y - y0f, wy0 = 1.f - wy1;
        const float ap = aw[p];

        const int   xc[4] = { x0, x0 + 1, x0,     x0 + 1 };
        const int   yc[4] = { y0, y0,     y0 + 1, y0 + 1 };
        const float wc[4] = { wx0 * wy0, wx1 * wy0, wx0 * wy1, wx1 * wy1 };
#pragma unroll
        for (int cnr = 0; cnr < 4; cnr++) {
            if (xc[cnr] >= 0 && xc[cnr] < Wl && yc[cnr] >= 0 && yc[cnr] < Hl) {
                const float w = ap * wc[cnr];
                const float4 v = *(const float4*)&vb[(size_t)(yc[cnr] * Wl + xc[cnr]) * E_];
                acc.x = fmaf(w, v.x, acc.x);
                acc.y = fmaf(w, v.y, acc.y);
                acc.z = fmaf(w, v.z, acc.z);
                acc.w = fmaf(w, v.w, acc.w);
            }
        }
    }

    *(float4*)&g_o[(size_t)bq * E_ + c0] = acc;
}

// ---------------------------------------------------------------------------
extern "C" void kernel_launch(void* const* d_in, const int* in_sizes, int n_in,
                              void* d_out, int out_size)
{
    const float* query  = (const float*)d_in[0];
    const float* value  = (const float*)d_in[1];
    const float* ref2d  = (const float*)d_in[2];
    const int*   shapes = (const int*)  d_in[3];
    const float* W_off  = (const float*)d_in[4];
    const float* b_off  = (const float*)d_in[5];
    const float* W_attn = (const float*)d_in[6];
    const float* b_attn = (const float*)d_in[7];
    const float* W_val  = (const float*)d_in[8];
    const float* b_val  = (const float*)d_in[9];
    const float* W_out  = (const float*)d_in[10];
    const float* b_out  = (const float*)d_in[11];
    float* out = (float*)d_out;

    float *v_ptr, *off_ptr, *att_ptr, *o_ptr;
    cudaGetSymbolAddress((void**)&v_ptr,  g_v);
    cudaGetSymbolAddress((void**)&off_ptr, g_off);
    cudaGetSymbolAddress((void**)&att_ptr, g_att);
    cudaGetSymbolAddress((void**)&o_ptr,  g_o);

    // dynamic smem sizes: 2 stages of (128*36 + 32*(BN+4)) floats
    auto smem_bytes = [](int BN) {
        return (size_t)2 * (128 * 36 + 32 * (BN + 4)) * sizeof(float);
    };
    cudaFuncSetAttribute((const void*)gemm_mma<128, false>, cudaFuncAttributeMaxDynamicSharedMemorySize, (int)smem_bytes(128));
    cudaFuncSetAttribute((const void*)gemm_mma<128, true>,  cudaFuncAttributeMaxDynamicSharedMemorySize, (int)smem_bytes(128));
    cudaFuncSetAttribute((const void*)gemm_mma<64, false>,  cudaFuncAttributeMaxDynamicSharedMemorySize, (int)smem_bytes(64));
    cudaFuncSetAttribute((const void*)gemm_mma<32, false>,  cudaFuncAttributeMaxDynamicSharedMemorySize, (int)smem_bytes(32));

    const int Mv = B_ * NV_;   // 131072
    const int Mq = B_ * NQ_;   // 65536

    // 1) value projection: (Mv,256) @ (256,256)
    gemm_mma<128, false><<<dim3(2, Mv / 128), 256, smem_bytes(128)>>>(value, W_val, b_val, nullptr, v_ptr, Mv, E_);
    // 2) offset projection: (Mq,256) @ (256,64)
    gemm_mma<64, false><<<dim3(1, Mq / 128), 256, smem_bytes(64)>>>(query, W_off, b_off, nullptr, off_ptr, Mq, 64);
    // 3) attn projection: (Mq,256) @ (256,32)
    gemm_mma<32, false><<<dim3(1, Mq / 128), 256, smem_bytes(32)>>>(query, W_attn, b_attn, nullptr, att_ptr, Mq, 32);
    // 4) softmax + bilinear sampling -> g_o (one warp per (bq, half))
    {
        int warps = Mq * 2;                    // 131072
        int blocks = warps * 32 / 256;         // 16384
        sample_kernel<<<blocks, 256>>>(ref2d, shapes);
    }
    // 5) output projection + bias + residual -> d_out
    gemm_mma<128, true><<<dim3(2, Mq / 128), 256, smem_bytes(128)>>>(o_ptr, W_out, b_out, query, out, Mq, E_);
}

// round 4
// speedup vs baseline: 3.6196x; 1.2115x over previous
#include <cuda_runtime.h>
#include <cuda_fp16.h>
#include <cstdint>
#include <cmath>

// Problem constants (fixed by setup_inputs)
#define B_   8
#define NQ_  8192
#define E_   256
#define HN_  8
#define P_   4
#define DH_  32
#define NV_  16384   // 128*128

// Scratch (no cudaMalloc allowed)
__device__ __half g_v[(size_t)B_ * NV_ * E_];            // projected value, fp16 (B, NV, E)
__device__ float  g_oa[(size_t)B_ * NQ_ * 96];           // [off(64) | attn(32)] per query
__device__ float  g_o [(size_t)B_ * NQ_ * E_];           // sampled output pre-proj
__device__ float  g_wcat[E_ * 96];                       // [W_off | W_attn]
__device__ float  g_bcat[96];

// ---------------------------------------------------------------------------
// PTX helpers (arch-neutral: cp.async + mma.sync fp16; no tcgen05)
// ---------------------------------------------------------------------------
#define CP_ASYNC16(saddr, gaddr) \
    asm volatile("cp.async.cg.shared.global [%0], [%1], 16;" :: "r"(saddr), "l"(gaddr) : "memory")
#define CP_COMMIT() asm volatile("cp.async.commit_group;" ::: "memory")
template<int N>
__device__ __forceinline__ void cp_wait() {
    asm volatile("cp.async.wait_group %0;" :: "n"(N) : "memory");
}

__device__ __forceinline__ uint32_t smem_u32(const void* p) {
    uint32_t a;
    asm("{ .reg .u64 t; cvta.to.shared.u64 t, %1; cvt.u32.u64 %0, t; }" : "=r"(a) : "l"(p));
    return a;
}

// pack two fp32 -> f16x2 (lo = x, hi = y), round-to-nearest
__device__ __forceinline__ uint32_t pack_h2(float x, float y) {
    uint32_t r;
    asm("cvt.rn.f16x2.f32 %0, %2, %1;" : "=r"(r) : "f"(x), "f"(y));
    return r;
}

__device__ __forceinline__ void mma_f16(float d[4], const uint32_t a[4],
                                        uint32_t b0, uint32_t b1) {
    asm volatile(
        "mma.sync.aligned.m16n8k16.row.col.f32.f16.f16.f32 "
        "{%0,%1,%2,%3}, {%4,%5,%6,%7}, {%8,%9}, {%0,%1,%2,%3};"
        : "+f"(d[0]), "+f"(d[1]), "+f"(d[2]), "+f"(d[3])
        : "r"(a[0]), "r"(a[1]), "r"(a[2]), "r"(a[3]), "r"(b0), "r"(b1));
}

// ---------------------------------------------------------------------------
// GEMM: C(M,N) = A(M,K=256) @ W(K=256,N) + bias (+R if RESID)
// fp16 mma m16n8k16, fp32 accumulate. Tile 128 x BN, BK=32, 8 warps,
// warp tile 32 x BN/2, 2-stage cp.async pipeline. OHALF: store C as __half.
// ---------------------------------------------------------------------------
template<int BN, bool RESID, bool OHALF>
__global__ __launch_bounds__(256, 2)
void gemm_mma(const float* __restrict__ A, const float* __restrict__ W,
              const float* __restrict__ bias, const float* __restrict__ R,
              void* __restrict__ Cv, int M, int N)
{
    constexpr int BM = 128, BK = 32, NIT = E_ / BK;       // 8 iterations
    constexpr int AP = BK + 4;                            // padded A row (floats)
    constexpr int BP = BN + 4;
    constexpr int ASZ = BM * AP;
    constexpr int BSZ = BK * BP;
    constexpr int NT  = BN / 16;                          // n-tiles per warp

    extern __shared__ float smem[];
    float* const As0 = smem;
    float* const Bs0 = smem + ASZ;
    float* const As1 = smem + ASZ + BSZ;
    float* const Bs1 = smem + 2 * ASZ + BSZ;

    const int tid  = threadIdx.x;
    const int wid  = tid >> 5;
    const int lane = tid & 31;
    const int gid  = lane >> 2;
    const int tig  = lane & 3;

    const int row0 = blockIdx.y * BM;
    const int col0 = blockIdx.x * BN;
    const int wr0  = (wid & 3) * 32;
    const int wc0  = (wid >> 2) * (BN / 2);

    const uint32_t sA[2] = { smem_u32(As0), smem_u32(As1) };
    const uint32_t sB[2] = { smem_u32(Bs0), smem_u32(Bs1) };

    float acc[2][NT][4];
#pragma unroll
    for (int mt = 0; mt < 2; mt++)
#pragma unroll
        for (int nt = 0; nt < NT; nt++)
#pragma unroll
            for (int i = 0; i < 4; i++) acc[mt][nt][i] = 0.f;

    auto load_tile = [&](int s, int k0) {
        const float* Ab = A + (size_t)row0 * E_ + k0;
#pragma unroll
        for (int i = 0; i < 4; i++) {
            int idx = tid + i * 256;
            int r = idx >> 3, c4 = idx & 7;
            CP_ASYNC16(sA[s] + (uint32_t)(r * AP + c4 * 4) * 4, Ab + (size_t)r * E_ + c4 * 4);
        }
        const float* Wb = W + (size_t)k0 * N + col0;
#pragma unroll
        for (int i = 0; i < BN / 32; i++) {
            int idx = tid + i * 256;
            int r = idx / (BN / 4), c4 = idx % (BN / 4);
            CP_ASYNC16(sB[s] + (uint32_t)(r * BP + c4 * 4) * 4, Wb + (size_t)r * N + c4 * 4);
        }
    };

    auto compute_tile = [&](int s) {
        const float* Asp = (s == 0) ? As0 : As1;
        const float* Bsp = (s == 0) ? Bs0 : Bs1;
#pragma unroll
        for (int ks = 0; ks < BK / 16; ks++) {
            const int k0 = ks * 16;
            const int ke = k0 + 2 * tig;
            uint32_t af[2][4];
#pragma unroll
            for (int mt = 0; mt < 2; mt++) {
                const int r = wr0 + mt * 16 + gid;
                const float2 v0 = *(const float2*)&Asp[r * AP + ke];
                const float2 v1 = *(const float2*)&Asp[(r + 8) * AP + ke];
                const float2 v2 = *(const float2*)&Asp[r * AP + ke + 8];
                const float2 v3 = *(const float2*)&Asp[(r + 8) * AP + ke + 8];
                af[mt][0] = pack_h2(v0.x, v0.y);
                af[mt][1] = pack_h2(v1.x, v1.y);
                af[mt][2] = pack_h2(v2.x, v2.y);
                af[mt][3] = pack_h2(v3.x, v3.y);
            }
#pragma unroll
            for (int nt = 0; nt < NT; nt++) {
                const int c = wc0 + nt * 8 + gid;
                const uint32_t b0 = pack_h2(Bsp[ke * BP + c],       Bsp[(ke + 1) * BP + c]);
                const uint32_t b1 = pack_h2(Bsp[(ke + 8) * BP + c], Bsp[(ke + 9) * BP + c]);
                mma_f16(acc[0][nt], af[0], b0, b1);
                mma_f16(acc[1][nt], af[1], b0, b1);
            }
        }
    };

    load_tile(0, 0); CP_COMMIT();
#pragma unroll
    for (int it = 0; it < NIT; it++) {
        if (it + 1 < NIT) {
            load_tile((it + 1) & 1, (it + 1) * BK); CP_COMMIT();
            cp_wait<1>();
        } else {
            cp_wait<0>();
        }
        __syncthreads();
        compute_tile(it & 1);
        __syncthreads();
    }

    // epilogue
    float*   Cf = (float*)Cv;
    __half2* Ch = (__half2*)Cv;
#pragma unroll
    for (int mt = 0; mt < 2; mt++) {
#pragma unroll
        for (int nt = 0; nt < NT; nt++) {
            const int c = col0 + wc0 + nt * 8 + 2 * tig;
            const float bx = bias[c], by = bias[c + 1];
            const int r0 = row0 + wr0 + mt * 16 + gid;
            float2 o0 = { acc[mt][nt][0] + bx, acc[mt][nt][1] + by };
            float2 o1 = { acc[mt][nt][2] + bx, acc[mt][nt][3] + by };
            if (RESID) {
                const float2 rv0 = *(const float2*)&R[(size_t)r0 * N + c];
                const float2 rv1 = *(const float2*)&R[(size_t)(r0 + 8) * N + c];
                o0.x += rv0.x; o0.y += rv0.y;
                o1.x += rv1.x; o1.y += rv1.y;
            }
            if (OHALF) {
                Ch[((size_t)r0 * N + c) >> 1]       = __floats2half2_rn(o0.x, o0.y);
                Ch[((size_t)(r0 + 8) * N + c) >> 1] = __floats2half2_rn(o1.x, o1.y);
            } else {
                *(float2*)&Cf[(size_t)r0 * N + c]       = o0;
                *(float2*)&Cf[(size_t)(r0 + 8) * N + c] = o1;
            }
        }
    }
}

// ---------------------------------------------------------------------------
// Concat [W_off | W_attn] -> g_wcat (256 x 96), biases -> g_bcat
// ---------------------------------------------------------------------------
__global__ void concat_wb(const float* __restrict__ Wo, const float* __restrict__ Wa,
                          const float* __restrict__ bo, const float* __restrict__ ba)
{
    const int t = blockIdx.x * blockDim.x + threadIdx.x;
    if (t < E_ * 96) {
        const int k = t / 96, n = t % 96;
        g_wcat[t] = (n < 64) ? Wo[k * 64 + n] : Wa[k * 32 + (n - 64)];
    }
    if (t < 96) g_bcat[t] = (t < 64) ? bo[t] : ba[t - 64];
}

// ---------------------------------------------------------------------------
// Sampling: one warp per (bq, half). lane handles 4 channels (half4 = 8B).
// Branchless: clamp coords, zero weight when out of bounds.
// ---------------------------------------------------------------------------
__global__ __launch_bounds__(256)
void sample_kernel(const float* __restrict__ ref2d, const int* __restrict__ shapes)
{
    const int gtid = blockIdx.x * blockDim.x + threadIdx.x;
    const int warp = gtid >> 5;
    const int lane = gtid & 31;
    const int bq   = warp >> 1;
    const int half = warp & 1;
    if (bq >= B_ * NQ_) return;
    const int b = bq >> 13;                     // NQ_ = 8192

    const int h  = half * 4 + (lane >> 3);      // head 0..7
    const int c0 = h * DH_ + (lane & 7) * 4;    // channel base (4 ch)

    const int Hl = shapes[0], Wl = shapes[1];
    const float fW = (float)Wl, fH = (float)Hl;

    const float rx = ref2d[(size_t)bq * 2 + 0];
    const float ry = ref2d[(size_t)bq * 2 + 1];

    const float* qa = g_oa + (size_t)bq * 96;
    // softmax over P=4 logits
    const float4 lg = *(const float4*)&qa[64 + h * 4];
    const float mx = fmaxf(fmaxf(lg.x, lg.y), fmaxf(lg.z, lg.w));
    const float e0 = __expf(lg.x - mx), e1 = __expf(lg.y - mx),
                e2 = __expf(lg.z - mx), e3 = __expf(lg.w - mx);
    const float inv = 1.f / (e0 + e1 + e2 + e3);
    const float aw[P_] = { e0 * inv, e1 * inv, e2 * inv, e3 * inv };

    // offsets: 8 floats contiguous per (bq, h)
    const float4 of0 = *(const float4*)&qa[h * 8];
    const float4 of1 = *(const float4*)&qa[h * 8 + 4];
    const float ox[P_] = { of0.x, of0.z, of1.x, of1.z };
    const float oy[P_] = { of0.y, of0.w, of1.y, of1.w };

    const __half* vb = g_v + (size_t)b * NV_ * E_ + c0;

    float4 acc = { 0.f, 0.f, 0.f, 0.f };
#pragma unroll
    for (int p = 0; p < P_; p++) {
        const float x = fmaf(rx, fW, ox[p]) - 0.5f;
        const float y = fmaf(ry, fH, oy[p]) - 0.5f;
        const float x0f = floorf(x), y0f = floorf(y);
        const int x0 = (int)x0f, y0 = (int)y0f;
        const float wx1 = x - x0f, wx0 = 1.f - wx1;
        const float wy1 = y - y0f, wy0 = 1.f - wy1;
        const float ap = aw[p];

        const int   xc[4] = { x0, x0 + 1, x0,     x0 + 1 };
        const int   yc[4] = { y0, y0,     y0 + 1, y0 + 1 };
        const float wc[4] = { wx0 * wy0, wx1 * wy0, wx0 * wy1, wx1 * wy1 };
#pragma unroll
        for (int cnr = 0; cnr < 4; cnr++) {
            const bool ok = (xc[cnr] >= 0) & (xc[cnr] < Wl) & (yc[cnr] >= 0) & (yc[cnr] < Hl);
            const int xi = min(max(xc[cnr], 0), Wl - 1);
            const int yi = min(max(yc[cnr], 0), Hl - 1);
            const float w = ok ? ap * wc[cnr] : 0.f;
            // 4 halves = 8B load
            const uint2 raw = *(const uint2*)&vb[(size_t)(yi * Wl + xi) * E_];
            const float2 f01 = __half22float2(*(const __half2*)&raw.x);
            const float2 f23 = __half22float2(*(const __half2*)&raw.y);
            acc.x = fmaf(w, f01.x, acc.x);
            acc.y = fmaf(w, f01.y, acc.y);
            acc.z = fmaf(w, f23.x, acc.z);
            acc.w = fmaf(w, f23.y, acc.w);
        }
    }

    *(float4*)&g_o[(size_t)bq * E_ + c0] = acc;
}

// ---------------------------------------------------------------------------
extern "C" void kernel_launch(void* const* d_in, const int* in_sizes, int n_in,
                              void* d_out, int out_size)
{
    const float* query  = (const float*)d_in[0];
    const float* value  = (const float*)d_in[1];
    const float* ref2d  = (const float*)d_in[2];
    const int*   shapes = (const int*)  d_in[3];
    const float* W_off  = (const float*)d_in[4];
    const float* b_off  = (const float*)d_in[5];
    const float* W_attn = (const float*)d_in[6];
    const float* b_attn = (const float*)d_in[7];
    const float* W_val  = (const float*)d_in[8];
    const float* b_val  = (const float*)d_in[9];
    const float* W_out  = (const float*)d_in[10];
    const float* b_out  = (const float*)d_in[11];
    float* out = (float*)d_out;

    void *v_ptr, *oa_ptr, *o_ptr, *wc_ptr, *bc_ptr;
    cudaGetSymbolAddress(&v_ptr,  g_v);
    cudaGetSymbolAddress(&oa_ptr, g_oa);
    cudaGetSymbolAddress(&o_ptr,  g_o);
    cudaGetSymbolAddress(&wc_ptr, g_wcat);
    cudaGetSymbolAddress(&bc_ptr, g_bcat);

    auto smem_bytes = [](int BN) {
        return (size_t)2 * (128 * 36 + 32 * (BN + 4)) * sizeof(float);
    };
    cudaFuncSetAttribute((const void*)gemm_mma<128, false, true>, cudaFuncAttributeMaxDynamicSharedMemorySize, (int)smem_bytes(128));
    cudaFuncSetAttribute((const void*)gemm_mma<96, false, false>, cudaFuncAttributeMaxDynamicSharedMemorySize, (int)smem_bytes(96));
    cudaFuncSetAttribute((const void*)gemm_mma<128, true, false>, cudaFuncAttributeMaxDynamicSharedMemorySize, (int)smem_bytes(128));

    const int Mv = B_ * NV_;   // 131072
    const int Mq = B_ * NQ_;   // 65536

    // 0) concat off/attn weights
    concat_wb<<<96, 256>>>(W_off, W_attn, b_off, b_attn);

    // 1) value projection -> fp16 g_v: (Mv,256) @ (256,256)
    gemm_mma<128, false, true><<<dim3(2, Mv / 128), 256, smem_bytes(128)>>>(
        value, W_val, b_val, nullptr, v_ptr, Mv, E_);
    // 2) fused offset+attn projection: (Mq,256) @ (256,96)
    gemm_mma<96, false, false><<<dim3(1, Mq / 128), 256, smem_bytes(96)>>>(
        query, (const float*)wc_ptr, (const float*)bc_ptr, nullptr, oa_ptr, Mq, 96);
    // 3) softmax + bilinear sampling -> g_o
    {
        int warps = Mq * 2;
        int blocks = warps * 32 / 256;
        sample_kernel<<<blocks, 256>>>(ref2d, shapes);
    }
    // 4) output projection + bias + residual -> d_out
    gemm_mma<128, true, false><<<dim3(2, Mq / 128), 256, smem_bytes(128)>>>(
        (const float*)o_ptr, W_out, b_out, query, out, Mq, E_);
}

// round 6
// speedup vs baseline: 4.8939x; 1.3521x over previous
#include <cuda_runtime.h>
#include <cuda_fp16.h>
#include <cstdint>
#include <cmath>

// Problem constants (fixed by setup_inputs)
#define B_   8
#define NQ_  8192
#define E_   256
#define HN_  8
#define P_   4
#define DH_  32
#define NV_  16384   // 128*128

// Scratch (no cudaMalloc allowed)
__device__ __half g_v [(size_t)B_ * NV_ * E_];           // projected value, fp16
__device__ float  g_oa[(size_t)B_ * NQ_ * 96];           // [off(64) | attn(32)] per query
__device__ __half g_o [(size_t)B_ * NQ_ * E_];           // sampled output, fp16
__device__ __half g_wv16[E_ * E_];                       // W_val  fp16 [k][n]
__device__ __half g_wu16[E_ * E_];                       // W_out  fp16 [k][n]
__device__ __half g_wc16[E_ * 96];                       // [W_off|W_attn] fp16 [k][n]
__device__ float  g_bcat[96];

// ---------------------------------------------------------------------------
// PTX helpers (arch-neutral: cp.async + ldmatrix + mma.sync fp16)
// ---------------------------------------------------------------------------
#define CP_ASYNC16(saddr, gaddr) \
    asm volatile("cp.async.cg.shared.global [%0], [%1], 16;" :: "r"(saddr), "l"(gaddr) : "memory")
#define CP_COMMIT() asm volatile("cp.async.commit_group;" ::: "memory")
template<int N>
__device__ __forceinline__ void cp_wait() {
    asm volatile("cp.async.wait_group %0;" :: "n"(N) : "memory");
}

__device__ __forceinline__ uint32_t smem_u32(const void* p) {
    uint32_t a;
    asm("{ .reg .u64 t; cvta.to.shared.u64 t, %1; cvt.u32.u64 %0, t; }" : "=r"(a) : "l"(p));
    return a;
}

__device__ __forceinline__ uint32_t pack_h2(float x, float y) {
    uint32_t r;
    asm("cvt.rn.f16x2.f32 %0, %2, %1;" : "=r"(r) : "f"(x), "f"(y));
    return r;
}

#define LDMATRIX_X4(r, addr) \
    asm volatile("ldmatrix.sync.aligned.m8n8.x4.shared.b16 {%0,%1,%2,%3}, [%4];" \
        : "=r"((r)[0]), "=r"((r)[1]), "=r"((r)[2]), "=r"((r)[3]) : "r"(addr))
#define LDMATRIX_X4_T(r, addr) \
    asm volatile("ldmatrix.sync.aligned.m8n8.x4.trans.shared.b16 {%0,%1,%2,%3}, [%4];" \
        : "=r"((r)[0]), "=r"((r)[1]), "=r"((r)[2]), "=r"((r)[3]) : "r"(addr))
#define STS_V2(addr, x, y) \
    asm volatile("st.shared.v2.b32 [%0], {%1,%2};" :: "r"(addr), "r"(x), "r"(y) : "memory")

__device__ __forceinline__ void mma_f16(float d[4], const uint32_t a[4],
                                        uint32_t b0, uint32_t b1) {
    asm volatile(
        "mma.sync.aligned.m16n8k16.row.col.f32.f16.f16.f32 "
        "{%0,%1,%2,%3}, {%4,%5,%6,%7}, {%8,%9}, {%0,%1,%2,%3};"
        : "+f"(d[0]), "+f"(d[1]), "+f"(d[2]), "+f"(d[3])
        : "r"(a[0]), "r"(a[1]), "r"(a[2]), "r"(a[3]), "r"(b0), "r"(b1));
}

// ---------------------------------------------------------------------------
// GEMM: C(M,N) = A(M,K=256) @ Wh(K,N fp16) + bias (+R)
// fp16 smem + ldmatrix + mma.m16n8k16. Tile 128 x BN, BK=32, 8 warps.
// AHALF: A is fp16 in gmem (cp.async); else fp32 (LDG->cvt->STS pipeline).
// OHALF: write C as fp16.
// NOTE: __syncthreads() after compute(s) is load-bearing — it protects the
// just-consumed stage from the cp.async/STS writes issued for the next tiles.
// ---------------------------------------------------------------------------
template<int BN, bool AHALF, bool RESID, bool OHALF>
__global__ __launch_bounds__(256, 2)
void gemm_ldm(const void* __restrict__ Av, const __half* __restrict__ Wh,
              const float* __restrict__ bias, const float* __restrict__ R,
              void* __restrict__ Cv, int M, int N)
{
    constexpr int BM = 128, BK = 32, NIT = E_ / BK;     // 8 K-iterations
    constexpr int AP = BK + 8;                          // 40 halves (80B rows)
    constexpr int BP = BN + 8;                          // halves
    constexpr int ASZ = BM * AP;                        // halves per A stage
    constexpr int BSZ = BK * BP;
    constexpr int NTP = BN / 32;                        // ldmatrix n-pairs per warp

    __shared__ __half hs[2 * (ASZ + BSZ)];

    const int tid  = threadIdx.x;
    const int wid  = tid >> 5;
    const int lane = tid & 31;
    const int gid  = lane >> 2;
    const int tig  = lane & 3;

    const int row0 = blockIdx.y * BM;
    const int col0 = blockIdx.x * BN;
    const int wr0  = (wid & 3) * 32;
    const int wc0  = (wid >> 2) * (BN / 2);

    const uint32_t sbase = smem_u32(hs);
    const uint32_t sA[2] = { sbase, sbase + (uint32_t)(ASZ + BSZ) * 2 };
    const uint32_t sB[2] = { sbase + (uint32_t)ASZ * 2, sbase + (uint32_t)(2 * ASZ + BSZ) * 2 };

    const float*  Af = (const float*)Av;
    const __half* Ah = (const __half*)Av;

    float acc[2][BN / 16][4];
#pragma unroll
    for (int mt = 0; mt < 2; mt++)
#pragma unroll
        for (int nt = 0; nt < BN / 16; nt++)
#pragma unroll
            for (int i = 0; i < 4; i++) acc[mt][nt][i] = 0.f;

    float4 ar[4];   // fp32-A staging regs

    auto ldgA = [&](int k0) {
        if (!AHALF) {
#pragma unroll
            for (int i = 0; i < 4; i++) {
                int idx = tid + i * 256;
                int r = idx >> 3, c4 = idx & 7;
                ar[i] = *(const float4*)&Af[(size_t)(row0 + r) * E_ + k0 + c4 * 4];
            }
        }
    };
    auto stsA = [&](int s) {
        if (!AHALF) {
#pragma unroll
            for (int i = 0; i < 4; i++) {
                int idx = tid + i * 256;
                int r = idx >> 3, c4 = idx & 7;
                STS_V2(sA[s] + (uint32_t)(r * AP + c4 * 4) * 2,
                       pack_h2(ar[i].x, ar[i].y), pack_h2(ar[i].z, ar[i].w));
            }
        }
    };
    auto asyncA = [&](int s, int k0) {
        if (AHALF) {
#pragma unroll
            for (int i = 0; i < 2; i++) {
                int chunk = tid + i * 256;          // 512 chunks total
                int r = chunk >> 2, c8 = chunk & 3;
                CP_ASYNC16(sA[s] + (uint32_t)(r * AP + c8 * 8) * 2,
                           Ah + (size_t)(row0 + r) * E_ + k0 + c8 * 8);
            }
        }
    };
    auto asyncB = [&](int s, int k0) {
        constexpr int BCH = BK * BN / 8;
#pragma unroll
        for (int i = 0; i < (BCH + 255) / 256; i++) {
            int chunk = tid + i * 256;
            if ((BCH & 255) == 0 || chunk < BCH) {
                int r = chunk / (BN / 8), c8 = chunk % (BN / 8);
                CP_ASYNC16(sB[s] + (uint32_t)(r * BP + c8 * 8) * 2,
                           Wh + (size_t)(k0 + r) * N + col0 + c8 * 8);
            }
        }
    };

    auto compute = [&](int s) {
#pragma unroll
        for (int ks = 0; ks < 2; ks++) {
            uint32_t a0[4], a1[4];
            const uint32_t arow = (uint32_t)(lane & 15);
            const uint32_t kof  = (uint32_t)(ks * 16 + (lane >> 4) * 8);
            LDMATRIX_X4(a0, sA[s] + (uint32_t)((wr0 + arow) * AP + kof) * 2);
            LDMATRIX_X4(a1, sA[s] + (uint32_t)((wr0 + 16 + arow) * AP + kof) * 2);
#pragma unroll
            for (int ntp = 0; ntp < NTP; ntp++) {
                uint32_t bb[4];
                LDMATRIX_X4_T(bb, sB[s] + (uint32_t)((ks * 16 + (lane & 15)) * BP
                                   + wc0 + ntp * 16 + (lane >> 4) * 8) * 2);
                mma_f16(acc[0][2 * ntp],     a0, bb[0], bb[1]);
                mma_f16(acc[1][2 * ntp],     a1, bb[0], bb[1]);
                mma_f16(acc[0][2 * ntp + 1], a0, bb[2], bb[3]);
                mma_f16(acc[1][2 * ntp + 1], a1, bb[2], bb[3]);
            }
        }
    };

    // ---- prologue ----
    ldgA(0); asyncA(0, 0); asyncB(0, 0); CP_COMMIT();
    stsA(0);
    ldgA(BK); asyncA(1, BK); asyncB(1, BK); CP_COMMIT();
    cp_wait<1>(); __syncthreads();

    // ---- mainloop ----
#pragma unroll
    for (int it = 0; it < NIT; it++) {
        compute(it & 1);
        if (it + 1 < NIT) {
            __syncthreads();               // protect stage (it&1) before refill (WAR)
            stsA((it + 1) & 1);
            if (it + 2 < NIT) {
                ldgA((it + 2) * BK);
                asyncA(it & 1, (it + 2) * BK);
                asyncB(it & 1, (it + 2) * BK);
            }
            CP_COMMIT();
            cp_wait<1>(); __syncthreads();
        }
    }

    // ---- epilogue ----
    float*   Cf = (float*)Cv;
    __half2* Ch = (__half2*)Cv;
#pragma unroll
    for (int mt = 0; mt < 2; mt++) {
#pragma unroll
        for (int nt = 0; nt < BN / 16; nt++) {
            const int c = col0 + wc0 + nt * 8 + 2 * tig;
            const float bx = bias[c], by = bias[c + 1];
            const int r0 = row0 + wr0 + mt * 16 + gid;
            float2 o0 = { acc[mt][nt][0] + bx, acc[mt][nt][1] + by };
            float2 o1 = { acc[mt][nt][2] + bx, acc[mt][nt][3] + by };
            if (RESID) {
                const float2 rv0 = *(const float2*)&R[(size_t)r0 * N + c];
                const float2 rv1 = *(const float2*)&R[(size_t)(r0 + 8) * N + c];
                o0.x += rv0.x; o0.y += rv0.y;
                o1.x += rv1.x; o1.y += rv1.y;
            }
            if (OHALF) {
                Ch[((size_t)r0 * N + c) >> 1]       = __floats2half2_rn(o0.x, o0.y);
                Ch[((size_t)(r0 + 8) * N + c) >> 1] = __floats2half2_rn(o1.x, o1.y);
            } else {
                *(float2*)&Cf[(size_t)r0 * N + c]       = o0;
                *(float2*)&Cf[(size_t)(r0 + 8) * N + c] = o1;
            }
        }
    }
}

// ---------------------------------------------------------------------------
// Weight prep: fp16 conversion + off/attn concat + bias concat
// ---------------------------------------------------------------------------
__global__ void prep_weights(const float* __restrict__ Wv, const float* __restrict__ Wu,
                             const float* __restrict__ Wo, const float* __restrict__ Wa,
                             const float* __restrict__ bo, const float* __restrict__ ba)
{
    const int t = blockIdx.x * blockDim.x + threadIdx.x;
    if (t < E_ * E_) {
        g_wv16[t] = __float2half_rn(Wv[t]);
        g_wu16[t] = __float2half_rn(Wu[t]);
    }
    if (t < E_ * 96) {
        const int k = t / 96, n = t % 96;
        g_wc16[t] = __float2half_rn(n < 64 ? Wo[k * 64 + n] : Wa[k * 32 + (n - 64)]);
    }
    if (t < 96) g_bcat[t] = (t < 64) ? bo[t] : ba[t - 64];
}

// ---------------------------------------------------------------------------
// Sampling: ONE warp per (b,q). lane = 8 channels (uint4); head = lane>>2.
// Writes g_o as fp16.
// ---------------------------------------------------------------------------
__global__ __launch_bounds__(256)
void sample_kernel(const float* __restrict__ ref2d, const int* __restrict__ shapes)
{
    const int gtid = blockIdx.x * blockDim.x + threadIdx.x;
    const int bq   = gtid >> 5;
    const int lane = gtid & 31;
    if (bq >= B_ * NQ_) return;
    const int b = bq >> 13;                     // NQ_ = 8192

    const int h  = lane >> 2;                   // head 0..7
    const int c0 = h * DH_ + (lane & 3) * 8;    // channel base (8 ch)

    const int Hl = shapes[0], Wl = shapes[1];
    const float fW = (float)Wl, fH = (float)Hl;

    const float rx = ref2d[(size_t)bq * 2 + 0];
    const float ry = ref2d[(size_t)bq * 2 + 1];

    const float* qa = g_oa + (size_t)bq * 96;
    // softmax over P=4 logits (redundant across the 4 lanes of a head)
    const float4 lg = *(const float4*)&qa[64 + h * 4];
    const float mx = fmaxf(fmaxf(lg.x, lg.y), fmaxf(lg.z, lg.w));
    const float e0 = __expf(lg.x - mx), e1 = __expf(lg.y - mx),
                e2 = __expf(lg.z - mx), e3 = __expf(lg.w - mx);
    const float inv = 1.f / (e0 + e1 + e2 + e3);
    const float aw[P_] = { e0 * inv, e1 * inv, e2 * inv, e3 * inv };

    const float4 of0 = *(const float4*)&qa[h * 8];
    const float4 of1 = *(const float4*)&qa[h * 8 + 4];
    const float ox[P_] = { of0.x, of0.z, of1.x, of1.z };
    const float oy[P_] = { of0.y, of0.w, of1.y, of1.w };

    const __half* vb = g_v + (size_t)b * NV_ * E_ + c0;

    float acc[8] = {0.f, 0.f, 0.f, 0.f, 0.f, 0.f, 0.f, 0.f};
#pragma unroll
    for (int p = 0; p < P_; p++) {
        const float x = fmaf(rx, fW, ox[p]) - 0.5f;
        const float y = fmaf(ry, fH, oy[p]) - 0.5f;
        const float x0f = floorf(x), y0f = floorf(y);
        const int x0 = (int)x0f, y0 = (int)y0f;
        const float wx1 = x - x0f, wx0 = 1.f - wx1;
        const float wy1 = y - y0f, wy0 = 1.f - wy1;
        const float ap = aw[p];

        const int   xc[4] = { x0, x0 + 1, x0,     x0 + 1 };
        const int   yc[4] = { y0, y0,     y0 + 1, y0 + 1 };
        const float wc[4] = { wx0 * wy0, wx1 * wy0, wx0 * wy1, wx1 * wy1 };
#pragma unroll
        for (int cnr = 0; cnr < 4; cnr++) {
            const bool ok = (xc[cnr] >= 0) & (xc[cnr] < Wl) & (yc[cnr] >= 0) & (yc[cnr] < Hl);
            const int xi = min(max(xc[cnr], 0), Wl - 1);
            const int yi = min(max(yc[cnr], 0), Hl - 1);
            const float w = ok ? ap * wc[cnr] : 0.f;
            const uint4 raw = *(const uint4*)&vb[(size_t)(yi * Wl + xi) * E_];
            const float2 f0 = __half22float2(*(const __half2*)&raw.x);
            const float2 f1 = __half22float2(*(const __half2*)&raw.y);
            const float2 f2 = __half22float2(*(const __half2*)&raw.z);
            const float2 f3 = __half22float2(*(const __half2*)&raw.w);
            acc[0] = fmaf(w, f0.x, acc[0]); acc[1] = fmaf(w, f0.y, acc[1]);
            acc[2] = fmaf(w, f1.x, acc[2]); acc[3] = fmaf(w, f1.y, acc[3]);
            acc[4] = fmaf(w, f2.x, acc[4]); acc[5] = fmaf(w, f2.y, acc[5]);
            acc[6] = fmaf(w, f3.x, acc[6]); acc[7] = fmaf(w, f3.y, acc[7]);
        }
    }

    uint4 outp;
    outp.x = pack_h2(acc[0], acc[1]);
    outp.y = pack_h2(acc[2], acc[3]);
    outp.z = pack_h2(acc[4], acc[5]);
    outp.w = pack_h2(acc[6], acc[7]);
    *(uint4*)&g_o[(size_t)bq * E_ + c0] = outp;
}

// ---------------------------------------------------------------------------
extern "C" void kernel_launch(void* const* d_in, const int* in_sizes, int n_in,
                              void* d_out, int out_size)
{
    const float* query  = (const float*)d_in[0];
    const float* value  = (const float*)d_in[1];
    const float* ref2d  = (const float*)d_in[2];
    const int*   shapes = (const int*)  d_in[3];
    const float* W_off  = (const float*)d_in[4];
    const float* b_off  = (const float*)d_in[5];
    const float* W_attn = (const float*)d_in[6];
    const float* b_attn = (const float*)d_in[7];
    const float* W_val  = (const float*)d_in[8];
    const float* b_val  = (const float*)d_in[9];
    const float* W_out  = (const float*)d_in[10];
    const float* b_out  = (const float*)d_in[11];
    float* out = (float*)d_out;

    void *v_ptr, *oa_ptr, *o_ptr, *wv_ptr, *wu_ptr, *wc_ptr, *bc_ptr;
    cudaGetSymbolAddress(&v_ptr,  g_v);
    cudaGetSymbolAddress(&oa_ptr, g_oa);
    cudaGetSymbolAddress(&o_ptr,  g_o);
    cudaGetSymbolAddress(&wv_ptr, g_wv16);
    cudaGetSymbolAddress(&wu_ptr, g_wu16);
    cudaGetSymbolAddress(&wc_ptr, g_wc16);
    cudaGetSymbolAddress(&bc_ptr, g_bcat);

    const int Mv = B_ * NV_;   // 131072
    const int Mq = B_ * NQ_;   // 65536

    // 0) weight prep (fp16 + concat)
    prep_weights<<<256, 256>>>(W_val, W_out, W_off, W_attn, b_off, b_attn);

    // 1) value projection -> fp16 g_v: (Mv,256) @ (256,256)
    gemm_ldm<128, false, false, true><<<dim3(2, Mv / 128), 256>>>(
        value, (const __half*)wv_ptr, b_val, nullptr, v_ptr, Mv, E_);
    // 2) fused offset+attn projection: (Mq,256) @ (256,96) -> fp32 g_oa
    gemm_ldm<96, false, false, false><<<dim3(1, Mq / 128), 256>>>(
        query, (const __half*)wc_ptr, (const float*)bc_ptr, nullptr, oa_ptr, Mq, 96);
    // 3) softmax + bilinear sampling -> fp16 g_o (one warp per query)
    {
        int blocks = (Mq * 32) / 256;          // 8192
        sample_kernel<<<blocks, 256>>>(ref2d, shapes);
    }
    // 4) output projection + bias + residual -> fp32 d_out
    gemm_ldm<128, true, true, false><<<dim3(2, Mq / 128), 256>>>(
        o_ptr, (const __half*)wu_ptr, b_out, query, out, Mq, E_);
}